// round 13
// baseline (speedup 1.0000x reference)
#include <cuda_runtime.h>
#include <cuda_fp16.h>
#include <mma.h>
#include <cstdint>

using namespace nvcuda;

#define DCH 64
#define MAXN 131072
#define MAXE (1 << 21)

// Scratch (allocation-free rule: __device__ globals)
__device__ __align__(16) __half g_bufA[(size_t)MAXN * DCH]; // messages
__device__ __align__(16) __half g_bufB[(size_t)MAXN * DCH]; // finalized h
__device__ float g_dis[MAXN];
__device__ int   g_degE[MAXN];
__device__ int   g_rowptr[MAXN + 1];
__device__ int   g_cursor[MAXN];
__device__ int   g_col[MAXE];
__device__ int   g_bsum[256];

// ---------------------------------------------------------------------------
// Degree / normalization + CSR build
// ---------------------------------------------------------------------------
__global__ void count_deg_kernel(const int* __restrict__ dst, int E) {
    int i = blockIdx.x * blockDim.x + threadIdx.x;
    if (i < E) atomicAdd(&g_degE[dst[i]], 1);
}
// per-1024-chunk sums for the scan; also computes dis = rsqrt(deg+1)
__global__ void scanA_kernel(int n) {
    __shared__ int sh[256];
    int base = blockIdx.x * 1024 + threadIdx.x * 4;
    int s = 0;
#pragma unroll
    for (int i = 0; i < 4; i++) {
        int idx = base + i;
        if (idx < n) {
            int d = g_degE[idx];
            s += d;
            g_dis[idx] = rsqrtf((float)(d + 1));
        }
    }
    sh[threadIdx.x] = s;
    __syncthreads();
    for (int off = 128; off; off >>= 1) {
        if (threadIdx.x < off) sh[threadIdx.x] += sh[threadIdx.x + off];
        __syncthreads();
    }
    if (threadIdx.x == 0) g_bsum[blockIdx.x] = sh[0];
}
// warp-parallel exclusive scan of the <=256 block sums
__global__ void scanB_kernel(int nb, int n, int E) {
    int lid = threadIdx.x;  // 32 threads
    int carry = 0;
    for (int base = 0; base < nb; base += 32) {
        int i = base + lid;
        int v = (i < nb) ? g_bsum[i] : 0;
        int x = v;
#pragma unroll
        for (int off = 1; off < 32; off <<= 1) {
            int t = __shfl_up_sync(0xFFFFFFFF, x, off);
            if (lid >= off) x += t;
        }
        if (i < nb) g_bsum[i] = carry + x - v;  // exclusive
        carry += __shfl_sync(0xFFFFFFFF, x, 31);
    }
    if (lid == 0) g_rowptr[n] = E;
}
__global__ void scanC_kernel(int n) {
    __shared__ int sh[256];
    int base = blockIdx.x * 1024 + threadIdx.x * 4;
    int v[4]; int mysum = 0;
#pragma unroll
    for (int i = 0; i < 4; i++) {
        v[i] = (base + i < n) ? g_degE[base + i] : 0;
        mysum += v[i];
    }
    sh[threadIdx.x] = mysum;
    __syncthreads();
    for (int off = 1; off < 256; off <<= 1) {
        int t = (threadIdx.x >= off) ? sh[threadIdx.x - off] : 0;
        __syncthreads();
        sh[threadIdx.x] += t;
        __syncthreads();
    }
    int run = sh[threadIdx.x] - mysum + g_bsum[blockIdx.x];
#pragma unroll
    for (int i = 0; i < 4; i++) {
        if (base + i < n) {
            g_rowptr[base + i] = run;
            g_cursor[base + i] = run;
            run += v[i];
        }
    }
}
__global__ void fill_kernel(const int* __restrict__ src, const int* __restrict__ dst, int E) {
    int e = blockIdx.x * blockDim.x + threadIdx.x;
    if (e < E) {
        int pos = atomicAdd(&g_cursor[dst[e]], 1);
        g_col[pos] = src[e];
    }
}

// ---------------------------------------------------------------------------
// fp16 helpers
// ---------------------------------------------------------------------------
__device__ __forceinline__ void acc_h8(float* a, uint4 v) {
    __half2 h0 = *(__half2*)&v.x, h1 = *(__half2*)&v.y;
    __half2 h2 = *(__half2*)&v.z, h3 = *(__half2*)&v.w;
    float2 f0 = __half22float2(h0), f1 = __half22float2(h1);
    float2 f2 = __half22float2(h2), f3 = __half22float2(h3);
    a[0] += f0.x; a[1] += f0.y; a[2] += f1.x; a[3] += f1.y;
    a[4] += f2.x; a[5] += f2.y; a[6] += f3.x; a[7] += f3.y;
}

// Per-thread serial CSR gather: 8 threads per node, lane owns channels
// [c*8, c*8+8). Col reads are same-address within the group (coalescer
// merges); row reads of a group are one contiguous 128B line.
__device__ __forceinline__ void gather_node(float* a, const __half* __restrict__ buf,
                                            int r, int c) {
    const uint4* gb = (const uint4*)buf;
    acc_h8(a, gb[(size_t)r * 8 + c]);            // self-loop
    int e0 = __ldg(&g_rowptr[r]), e1 = __ldg(&g_rowptr[r + 1]);
#pragma unroll 4
    for (int e = e0; e < e1; e++) {
        int s = __ldg(&g_col[e]);
        acc_h8(a, gb[(size_t)s * 8 + c]);
    }
}

// ---------------------------------------------------------------------------
// Tensor-core GEMM core (tf32 wmma): xs[128x64] @ Ws[64x64] -> f16 msg.
// 8 warps; warp w owns output rows [w*16, w*16+16). Accumulator spilled back
// into xs after a barrier, then epilogue scales by dis and packs fp16.
// ---------------------------------------------------------------------------
__device__ __forceinline__ void gemm_core_mma(
    float* xs, const float* Ws, int base, int n, __half* __restrict__ dstbuf)
{
    int tid = threadIdx.x;
    int w = tid >> 5;   // warp 0..7

    wmma::fragment<wmma::accumulator, 16, 16, 8, float> c[4];
#pragma unroll
    for (int i = 0; i < 4; i++) wmma::fill_fragment(c[i], 0.0f);

#pragma unroll
    for (int k = 0; k < 8; k++) {
        wmma::fragment<wmma::matrix_a, 16, 16, 8, wmma::precision::tf32, wmma::row_major> a;
        wmma::load_matrix_sync(a, xs + (w * 16) * DCH + k * 8, DCH);
#pragma unroll
        for (int t = 0; t < a.num_elements; t++) a.x[t] = wmma::__float_to_tf32(a.x[t]);
#pragma unroll
        for (int nt = 0; nt < 4; nt++) {
            wmma::fragment<wmma::matrix_b, 16, 16, 8, wmma::precision::tf32, wmma::row_major> b;
            wmma::load_matrix_sync(b, Ws + (k * 8) * DCH + nt * 16, DCH);
#pragma unroll
            for (int t = 0; t < b.num_elements; t++) b.x[t] = wmma::__float_to_tf32(b.x[t]);
            wmma::mma_sync(c[nt], a, b, c[nt]);
        }
    }
    __syncthreads();   // all warps done reading xs
#pragma unroll
    for (int nt = 0; nt < 4; nt++)
        wmma::store_matrix_sync(xs + (w * 16) * DCH + nt * 16, c[nt], DCH, wmma::mem_row_major);
    __syncthreads();

    // epilogue: dis scaling + fp16 pack
    int cg = (tid & 15) * 4;
#pragma unroll
    for (int rep = 0; rep < 8; rep++) {
        int lr = (tid >> 4) + rep * 16;
        int r = base + lr;
        if (r < n) {
            float dr = g_dis[r];
            float4 v = *(float4*)(xs + lr * DCH + cg);
            __half2 h0 = __floats2half2_rn(dr * v.x, dr * v.y);
            __half2 h1 = __floats2half2_rn(dr * v.z, dr * v.w);
            *(uint2*)(dstbuf + (size_t)r * DCH + cg) =
                make_uint2(*(uint32_t*)&h0, *(uint32_t*)&h1);
        }
    }
}

// Layer-1 GEMM: fp32 dense input x -> msg in g_bufA
__global__ void __launch_bounds__(256) gemm1_kernel(
    const float* __restrict__ in, const float* __restrict__ W, int n)
{
    __shared__ float xs[128 * DCH];   // 32 KB
    __shared__ float Ws[DCH * DCH];   // 16 KB
    int tid = threadIdx.x;

#pragma unroll
    for (int i = 0; i < 4; i++)
        ((float4*)Ws)[tid + 256 * i] = ((const float4*)W)[tid + 256 * i];

    int base = blockIdx.x * 128;
    int cg = (tid & 15) * 4;
#pragma unroll
    for (int rep = 0; rep < 8; rep++) {
        int lr = (tid >> 4) + rep * 16;
        int r = base + lr;
        float4 v = make_float4(0.f, 0.f, 0.f, 0.f);
        if (r < n) v = *(const float4*)(in + (size_t)r * DCH + cg);
        *(float4*)(xs + lr * DCH + cg) = v;
    }
    __syncthreads();

    gemm_core_mma(xs, Ws, base, n, g_bufA);
}

// Middle GEMM: fp16 finalized h input -> msg in dstbuf
__global__ void __launch_bounds__(256) gemm_mid_kernel(
    const __half* __restrict__ h, __half* __restrict__ dstbuf,
    const float* __restrict__ W, int n)
{
    __shared__ float xs[128 * DCH];   // 32 KB
    __shared__ float Ws[DCH * DCH];   // 16 KB
    int tid = threadIdx.x;

#pragma unroll
    for (int i = 0; i < 4; i++)
        ((float4*)Ws)[tid + 256 * i] = ((const float4*)W)[tid + 256 * i];

    int base = blockIdx.x * 128;
    int cg = (tid & 15) * 4;
#pragma unroll
    for (int rep = 0; rep < 8; rep++) {
        int lr = (tid >> 4) + rep * 16;
        int r = base + lr;
        float4 v = make_float4(0.f, 0.f, 0.f, 0.f);
        if (r < n) {
            uint2 u = *(const uint2*)(h + (size_t)r * DCH + cg);
            float2 f0 = __half22float2(*(__half2*)&u.x);
            float2 f1 = __half22float2(*(__half2*)&u.y);
            v = make_float4(f0.x, f0.y, f1.x, f1.y);
        }
        *(float4*)(xs + lr * DCH + cg) = v;
    }
    __syncthreads();

    gemm_core_mma(xs, Ws, base, n, dstbuf);
}

// ---------------------------------------------------------------------------
// Middle gather: h[r] = f16( relu(dis[r]*sum(msg) + b) )   (barrier-free)
// ---------------------------------------------------------------------------
__global__ void __launch_bounds__(256) gather_mid_kernel(
    const __half* __restrict__ srcbuf, __half* __restrict__ dsth,
    const float* __restrict__ b, int n)
{
    int t = blockIdx.x * blockDim.x + threadIdx.x;
    int r = t >> 3;
    if (r >= n) return;
    int c = t & 7;

    float a[8] = {0, 0, 0, 0, 0, 0, 0, 0};
    gather_node(a, srcbuf, r, c);

    float dr = g_dis[r];
    float4 b0 = *(const float4*)(b + c * 8);
    float4 b1 = *(const float4*)(b + c * 8 + 4);
    float h0 = fmaxf(fmaf(dr, a[0], b0.x), 0.f);
    float h1 = fmaxf(fmaf(dr, a[1], b0.y), 0.f);
    float h2 = fmaxf(fmaf(dr, a[2], b0.z), 0.f);
    float h3 = fmaxf(fmaf(dr, a[3], b0.w), 0.f);
    float h4 = fmaxf(fmaf(dr, a[4], b1.x), 0.f);
    float h5 = fmaxf(fmaf(dr, a[5], b1.y), 0.f);
    float h6 = fmaxf(fmaf(dr, a[6], b1.z), 0.f);
    float h7 = fmaxf(fmaf(dr, a[7], b1.w), 0.f);
    __half2 p0 = __floats2half2_rn(h0, h1);
    __half2 p1 = __floats2half2_rn(h2, h3);
    __half2 p2 = __floats2half2_rn(h4, h5);
    __half2 p3 = __floats2half2_rn(h6, h7);
    uint4 o = make_uint4(*(uint32_t*)&p0, *(uint32_t*)&p1,
                         *(uint32_t*)&p2, *(uint32_t*)&p3);
    *(uint4*)(dsth + (size_t)r * DCH + c * 8) = o;
}

// ---------------------------------------------------------------------------
// Final gather: out[r] = dis[r]*sum(srcbuf) + b3   (fp32 output)
// ---------------------------------------------------------------------------
__global__ void __launch_bounds__(256) final_gather_kernel(
    const __half* __restrict__ srcbuf,
    const float* __restrict__ b, float* __restrict__ out, int n)
{
    int t = blockIdx.x * blockDim.x + threadIdx.x;
    int r = t >> 3;
    if (r >= n) return;
    int c = t & 7;

    float a[8] = {0, 0, 0, 0, 0, 0, 0, 0};
    gather_node(a, srcbuf, r, c);

    float dr = g_dis[r];
    float4 b0 = *(const float4*)(b + c * 8);
    float4 b1 = *(const float4*)(b + c * 8 + 4);
    float4 o0, o1;
    o0.x = fmaf(dr, a[0], b0.x); o0.y = fmaf(dr, a[1], b0.y);
    o0.z = fmaf(dr, a[2], b0.z); o0.w = fmaf(dr, a[3], b0.w);
    o1.x = fmaf(dr, a[4], b1.x); o1.y = fmaf(dr, a[5], b1.y);
    o1.z = fmaf(dr, a[6], b1.z); o1.w = fmaf(dr, a[7], b1.w);
    *(float4*)(out + (size_t)r * DCH + c * 8)     = o0;
    *(float4*)(out + (size_t)r * DCH + c * 8 + 4) = o1;
}

// ---------------------------------------------------------------------------
extern "C" void kernel_launch(void* const* d_in, const int* in_sizes, int n_in,
                              void* d_out, int out_size)
{
    const float* x  = (const float*)d_in[0];
    const int*   ei = (const int*)d_in[1];
    const float* W1 = (const float*)d_in[2];
    const float* b1 = (const float*)d_in[3];
    const float* W2 = (const float*)d_in[4];
    const float* b2 = (const float*)d_in[5];
    const float* W3 = (const float*)d_in[6];
    const float* b3 = (const float*)d_in[7];
    float* out = (float*)d_out;

    int n = in_sizes[0] / DCH;
    int E = in_sizes[1] / 2;
    const int* src = ei;
    const int* dst = ei + E;

    int nb_e   = (E + 255) / 256;
    int nb_sc  = (n + 1023) / 1024;
    int nb_gm  = (n + 127) / 128;
    int nb_gat = (int)(((long long)n * 8 + 255) / 256);

    // device pointers to the two buffers
    void* pA = nullptr; cudaGetSymbolAddress(&pA, g_bufA);
    void* pB = nullptr; cudaGetSymbolAddress(&pB, g_bufB);
    __half* bufA = (__half*)pA;
    __half* bufB = (__half*)pB;

    // normalization + CSR build (recomputed every call)
    void* degE_ptr = nullptr;
    cudaGetSymbolAddress(&degE_ptr, g_degE);
    cudaMemsetAsync(degE_ptr, 0, (size_t)n * sizeof(int));
    count_deg_kernel<<<nb_e, 256>>>(dst, E);
    scanA_kernel<<<nb_sc, 256>>>(n);           // also computes g_dis
    scanB_kernel<<<1, 32>>>(nb_sc, n, E);
    scanC_kernel<<<nb_sc, 256>>>(n);
    fill_kernel<<<nb_e, 256>>>(src, dst, E);

    // layer 1: dense GEMM (tensor cores) -> msg in bufA
    gemm1_kernel<<<nb_gm, 256>>>(x, W1, n);
    // gather1 + finalize(b1): h1 fp16 -> bufB
    gather_mid_kernel<<<nb_gat, 256>>>(bufA, bufB, b1, n);
    // layer 2 GEMM: h1 @ W2 -> msg in bufA
    gemm_mid_kernel<<<nb_gm, 256>>>(bufB, bufA, W2, n);
    // gather2 + finalize(b2): h2 fp16 -> bufB
    gather_mid_kernel<<<nb_gat, 256>>>(bufA, bufB, b2, n);
    // layer 3 GEMM: h2 @ W3 -> msg in bufA
    gemm_mid_kernel<<<nb_gm, 256>>>(bufB, bufA, W3, n);
    // output: gather msg + bias b3 (fp32)
    final_gather_kernel<<<nb_gat, 256>>>(bufA, b3, out, n);
}

// round 15
// speedup vs baseline: 1.0873x; 1.0873x over previous
#include <cuda_runtime.h>
#include <cuda_fp16.h>
#include <mma.h>
#include <cstdint>

using namespace nvcuda;

#define DCH 64
#define MAXN 131072
#define MAXE (1 << 21)

// Scratch (allocation-free rule: __device__ globals)
__device__ __align__(16) __half g_bufA[(size_t)MAXN * DCH]; // messages
__device__ __align__(16) __half g_bufB[(size_t)MAXN * DCH]; // finalized h
__device__ float g_dis[MAXN];
__device__ int   g_degE[MAXN];
__device__ int   g_rowptr[MAXN + 1];
__device__ int   g_cursor[MAXN];
__device__ int   g_col[MAXE];
__device__ int   g_bsum[256];

// ---------------------------------------------------------------------------
// Degree / normalization + CSR build
// ---------------------------------------------------------------------------
__global__ void count_deg_kernel(const int* __restrict__ dst, int E) {
    int i = blockIdx.x * blockDim.x + threadIdx.x;
    if (i < E) atomicAdd(&g_degE[dst[i]], 1);
}
// per-1024-chunk sums for the scan; also computes dis = rsqrt(deg+1)
__global__ void scanA_kernel(int n) {
    __shared__ int sh[256];
    int base = blockIdx.x * 1024 + threadIdx.x * 4;
    int s = 0;
#pragma unroll
    for (int i = 0; i < 4; i++) {
        int idx = base + i;
        if (idx < n) {
            int d = g_degE[idx];
            s += d;
            g_dis[idx] = rsqrtf((float)(d + 1));
        }
    }
    sh[threadIdx.x] = s;
    __syncthreads();
    for (int off = 128; off; off >>= 1) {
        if (threadIdx.x < off) sh[threadIdx.x] += sh[threadIdx.x + off];
        __syncthreads();
    }
    if (threadIdx.x == 0) g_bsum[blockIdx.x] = sh[0];
}
// warp-parallel exclusive scan of the <=256 block sums
__global__ void scanB_kernel(int nb, int n, int E) {
    int lid = threadIdx.x;  // 32 threads
    int carry = 0;
    for (int base = 0; base < nb; base += 32) {
        int i = base + lid;
        int v = (i < nb) ? g_bsum[i] : 0;
        int x = v;
#pragma unroll
        for (int off = 1; off < 32; off <<= 1) {
            int t = __shfl_up_sync(0xFFFFFFFF, x, off);
            if (lid >= off) x += t;
        }
        if (i < nb) g_bsum[i] = carry + x - v;  // exclusive
        carry += __shfl_sync(0xFFFFFFFF, x, 31);
    }
    if (lid == 0) g_rowptr[n] = E;
}
__global__ void scanC_kernel(int n) {
    __shared__ int sh[256];
    int base = blockIdx.x * 1024 + threadIdx.x * 4;
    int v[4]; int mysum = 0;
#pragma unroll
    for (int i = 0; i < 4; i++) {
        v[i] = (base + i < n) ? g_degE[base + i] : 0;
        mysum += v[i];
    }
    sh[threadIdx.x] = mysum;
    __syncthreads();
    for (int off = 1; off < 256; off <<= 1) {
        int t = (threadIdx.x >= off) ? sh[threadIdx.x - off] : 0;
        __syncthreads();
        sh[threadIdx.x] += t;
        __syncthreads();
    }
    int run = sh[threadIdx.x] - mysum + g_bsum[blockIdx.x];
#pragma unroll
    for (int i = 0; i < 4; i++) {
        if (base + i < n) {
            g_rowptr[base + i] = run;
            g_cursor[base + i] = run;
            run += v[i];
        }
    }
}
__global__ void fill_kernel(const int* __restrict__ src, const int* __restrict__ dst, int E) {
    int e = blockIdx.x * blockDim.x + threadIdx.x;
    if (e < E) {
        int pos = atomicAdd(&g_cursor[dst[e]], 1);
        g_col[pos] = src[e];
    }
}

// ---------------------------------------------------------------------------
// fp16 helpers
// ---------------------------------------------------------------------------
__device__ __forceinline__ void acc_h8(float* a, uint4 v) {
    __half2 h0 = *(__half2*)&v.x, h1 = *(__half2*)&v.y;
    __half2 h2 = *(__half2*)&v.z, h3 = *(__half2*)&v.w;
    float2 f0 = __half22float2(h0), f1 = __half22float2(h1);
    float2 f2 = __half22float2(h2), f3 = __half22float2(h3);
    a[0] += f0.x; a[1] += f0.y; a[2] += f1.x; a[3] += f1.y;
    a[4] += f2.x; a[5] += f2.y; a[6] += f3.x; a[7] += f3.y;
}

// Per-thread serial CSR gather: 8 threads per node, lane owns channels
// [c*8, c*8+8). Col reads are same-address within the group (coalescer
// merges); row reads of a group are one contiguous 128B line.
__device__ __forceinline__ void gather_node(float* a, const __half* __restrict__ buf,
                                            int r, int c) {
    const uint4* gb = (const uint4*)buf;
    acc_h8(a, gb[(size_t)r * 8 + c]);            // self-loop
    int e0 = __ldg(&g_rowptr[r]), e1 = __ldg(&g_rowptr[r + 1]);
#pragma unroll 4
    for (int e = e0; e < e1; e++) {
        int s = __ldg(&g_col[e]);
        acc_h8(a, gb[(size_t)s * 8 + c]);
    }
}

// ---------------------------------------------------------------------------
// HMMA GEMM core: xs[128x64 f16, rows pre-scaled by dis] @ Ws[64x64 f16]
// -> fp16 msg. 8 warps; warp w owns rows [w*16, w*16+16). m16n16k16, fp32 acc.
// Epilogue drains each 16x16 accum tile through a per-warp float patch
// (warp-synchronous only, no block barriers).
// ---------------------------------------------------------------------------
__device__ __forceinline__ void gemm_core_hmma(
    const __half* xs, const __half* Ws, float* patch,
    int base, int n, __half* __restrict__ dstbuf)
{
    int tid = threadIdx.x;
    int w = tid >> 5;
    int lane = tid & 31;

    wmma::fragment<wmma::accumulator, 16, 16, 16, float> c[4];
#pragma unroll
    for (int i = 0; i < 4; i++) wmma::fill_fragment(c[i], 0.0f);

#pragma unroll
    for (int k = 0; k < 4; k++) {
        wmma::fragment<wmma::matrix_a, 16, 16, 16, __half, wmma::row_major> a;
        wmma::load_matrix_sync(a, xs + (w * 16) * DCH + k * 16, DCH);
#pragma unroll
        for (int nt = 0; nt < 4; nt++) {
            wmma::fragment<wmma::matrix_b, 16, 16, 16, __half, wmma::row_major> b;
            wmma::load_matrix_sync(b, Ws + (k * 16) * DCH + nt * 16, DCH);
            wmma::mma_sync(c[nt], a, b, c[nt]);
        }
    }

    float* pw = patch + w * 256;   // per-warp 16x16 float staging
    int prow = lane >> 1;
    int pcol = (lane & 1) * 8;
    int r = base + w * 16 + prow;
#pragma unroll
    for (int nt = 0; nt < 4; nt++) {
        wmma::store_matrix_sync(pw, c[nt], 16, wmma::mem_row_major);
        __syncwarp();
        float4 v0 = *(float4*)(pw + prow * 16 + pcol);
        float4 v1 = *(float4*)(pw + prow * 16 + pcol + 4);
        if (r < n) {
            __half2 h0 = __floats2half2_rn(v0.x, v0.y);
            __half2 h1 = __floats2half2_rn(v0.z, v0.w);
            __half2 h2 = __floats2half2_rn(v1.x, v1.y);
            __half2 h3 = __floats2half2_rn(v1.z, v1.w);
            *(uint4*)(dstbuf + (size_t)r * DCH + nt * 16 + pcol) =
                make_uint4(*(uint32_t*)&h0, *(uint32_t*)&h1,
                           *(uint32_t*)&h2, *(uint32_t*)&h3);
        }
        __syncwarp();   // patch reuse
    }
}

// stage W (fp32 global) -> fp16 smem [64x64]
__device__ __forceinline__ void stage_W_f16(__half* Ws, const float* __restrict__ W) {
    int tid = threadIdx.x;
#pragma unroll
    for (int i = 0; i < 2; i++) {
        int idx = tid + i * 256;        // 8 floats each
        float4 f0 = ((const float4*)W)[idx * 2];
        float4 f1 = ((const float4*)W)[idx * 2 + 1];
        __half2 h0 = __floats2half2_rn(f0.x, f0.y);
        __half2 h1 = __floats2half2_rn(f0.z, f0.w);
        __half2 h2 = __floats2half2_rn(f1.x, f1.y);
        __half2 h3 = __floats2half2_rn(f1.z, f1.w);
        *(uint4*)(Ws + idx * 8) = make_uint4(*(uint32_t*)&h0, *(uint32_t*)&h1,
                                             *(uint32_t*)&h2, *(uint32_t*)&h3);
    }
}

// Layer-1 GEMM: fp32 dense x -> msg in g_bufA.  xs = f16(dis * x)
__global__ void __launch_bounds__(256) gemm1_kernel(
    const float* __restrict__ in, const float* __restrict__ W, int n)
{
    __shared__ __half xs[128 * DCH];    // 16 KB
    __shared__ __half Ws[DCH * DCH];    // 8 KB
    __shared__ float  patch[8 * 256];   // 8 KB
    int tid = threadIdx.x;

    stage_W_f16(Ws, W);

    int base = blockIdx.x * 128;
    int c8 = (tid & 7) * 8;
#pragma unroll
    for (int rep = 0; rep < 4; rep++) {
        int lr = (tid >> 3) + rep * 32;
        int r = base + lr;
        uint4 o = make_uint4(0, 0, 0, 0);
        if (r < n) {
            float dr = g_dis[r];
            float4 f0 = *(const float4*)(in + (size_t)r * DCH + c8);
            float4 f1 = *(const float4*)(in + (size_t)r * DCH + c8 + 4);
            __half2 h0 = __floats2half2_rn(dr * f0.x, dr * f0.y);
            __half2 h1 = __floats2half2_rn(dr * f0.z, dr * f0.w);
            __half2 h2 = __floats2half2_rn(dr * f1.x, dr * f1.y);
            __half2 h3 = __floats2half2_rn(dr * f1.z, dr * f1.w);
            o = make_uint4(*(uint32_t*)&h0, *(uint32_t*)&h1,
                           *(uint32_t*)&h2, *(uint32_t*)&h3);
        }
        *(uint4*)(xs + lr * DCH + c8) = o;
    }
    __syncthreads();

    gemm_core_hmma(xs, Ws, patch, base, n, g_bufA);
}

// Middle GEMM: fp16 finalized h -> msg in dstbuf.  xs = f16(dis * h)
__global__ void __launch_bounds__(256) gemm_mid_kernel(
    const __half* __restrict__ h, __half* __restrict__ dstbuf,
    const float* __restrict__ W, int n)
{
    __shared__ __half xs[128 * DCH];    // 16 KB
    __shared__ __half Ws[DCH * DCH];    // 8 KB
    __shared__ float  patch[8 * 256];   // 8 KB
    int tid = threadIdx.x;

    stage_W_f16(Ws, W);

    int base = blockIdx.x * 128;
    int c8 = (tid & 7) * 8;
#pragma unroll
    for (int rep = 0; rep < 4; rep++) {
        int lr = (tid >> 3) + rep * 32;
        int r = base + lr;
        uint4 o = make_uint4(0, 0, 0, 0);
        if (r < n) {
            float dr = g_dis[r];
            uint4 u = *(const uint4*)(h + (size_t)r * DCH + c8);
            float2 f0 = __half22float2(*(__half2*)&u.x);
            float2 f1 = __half22float2(*(__half2*)&u.y);
            float2 f2 = __half22float2(*(__half2*)&u.z);
            float2 f3 = __half22float2(*(__half2*)&u.w);
            __half2 h0 = __floats2half2_rn(dr * f0.x, dr * f0.y);
            __half2 h1 = __floats2half2_rn(dr * f1.x, dr * f1.y);
            __half2 h2 = __floats2half2_rn(dr * f2.x, dr * f2.y);
            __half2 h3 = __floats2half2_rn(dr * f3.x, dr * f3.y);
            o = make_uint4(*(uint32_t*)&h0, *(uint32_t*)&h1,
                           *(uint32_t*)&h2, *(uint32_t*)&h3);
        }
        *(uint4*)(xs + lr * DCH + c8) = o;
    }
    __syncthreads();

    gemm_core_hmma(xs, Ws, patch, base, n, dstbuf);
}

// ---------------------------------------------------------------------------
// Middle gather: h[r] = f16( relu(dis[r]*sum(msg) + b) )   (barrier-free)
// ---------------------------------------------------------------------------
__global__ void __launch_bounds__(256) gather_mid_kernel(
    const __half* __restrict__ srcbuf, __half* __restrict__ dsth,
    const float* __restrict__ b, int n)
{
    int t = blockIdx.x * blockDim.x + threadIdx.x;
    int r = t >> 3;
    if (r >= n) return;
    int c = t & 7;

    float a[8] = {0, 0, 0, 0, 0, 0, 0, 0};
    gather_node(a, srcbuf, r, c);

    float dr = g_dis[r];
    float4 b0 = *(const float4*)(b + c * 8);
    float4 b1 = *(const float4*)(b + c * 8 + 4);
    float h0 = fmaxf(fmaf(dr, a[0], b0.x), 0.f);
    float h1 = fmaxf(fmaf(dr, a[1], b0.y), 0.f);
    float h2 = fmaxf(fmaf(dr, a[2], b0.z), 0.f);
    float h3 = fmaxf(fmaf(dr, a[3], b0.w), 0.f);
    float h4 = fmaxf(fmaf(dr, a[4], b1.x), 0.f);
    float h5 = fmaxf(fmaf(dr, a[5], b1.y), 0.f);
    float h6 = fmaxf(fmaf(dr, a[6], b1.z), 0.f);
    float h7 = fmaxf(fmaf(dr, a[7], b1.w), 0.f);
    __half2 p0 = __floats2half2_rn(h0, h1);
    __half2 p1 = __floats2half2_rn(h2, h3);
    __half2 p2 = __floats2half2_rn(h4, h5);
    __half2 p3 = __floats2half2_rn(h6, h7);
    uint4 o = make_uint4(*(uint32_t*)&p0, *(uint32_t*)&p1,
                         *(uint32_t*)&p2, *(uint32_t*)&p3);
    *(uint4*)(dsth + (size_t)r * DCH + c * 8) = o;
}

// ---------------------------------------------------------------------------
// Final gather: out[r] = dis[r]*sum(srcbuf) + b3   (fp32 output)
// ---------------------------------------------------------------------------
__global__ void __launch_bounds__(256) final_gather_kernel(
    const __half* __restrict__ srcbuf,
    const float* __restrict__ b, float* __restrict__ out, int n)
{
    int t = blockIdx.x * blockDim.x + threadIdx.x;
    int r = t >> 3;
    if (r >= n) return;
    int c = t & 7;

    float a[8] = {0, 0, 0, 0, 0, 0, 0, 0};
    gather_node(a, srcbuf, r, c);

    float dr = g_dis[r];
    float4 b0 = *(const float4*)(b + c * 8);
    float4 b1 = *(const float4*)(b + c * 8 + 4);
    float4 o0, o1;
    o0.x = fmaf(dr, a[0], b0.x); o0.y = fmaf(dr, a[1], b0.y);
    o0.z = fmaf(dr, a[2], b0.z); o0.w = fmaf(dr, a[3], b0.w);
    o1.x = fmaf(dr, a[4], b1.x); o1.y = fmaf(dr, a[5], b1.y);
    o1.z = fmaf(dr, a[6], b1.z); o1.w = fmaf(dr, a[7], b1.w);
    *(float4*)(out + (size_t)r * DCH + c * 8)     = o0;
    *(float4*)(out + (size_t)r * DCH + c * 8 + 4) = o1;
}

// ---------------------------------------------------------------------------
extern "C" void kernel_launch(void* const* d_in, const int* in_sizes, int n_in,
                              void* d_out, int out_size)
{
    const float* x  = (const float*)d_in[0];
    const int*   ei = (const int*)d_in[1];
    const float* W1 = (const float*)d_in[2];
    const float* b1 = (const float*)d_in[3];
    const float* W2 = (const float*)d_in[4];
    const float* b2 = (const float*)d_in[5];
    const float* W3 = (const float*)d_in[6];
    const float* b3 = (const float*)d_in[7];
    float* out = (float*)d_out;

    int n = in_sizes[0] / DCH;
    int E = in_sizes[1] / 2;
    const int* src = ei;
    const int* dst = ei + E;

    int nb_e   = (E + 255) / 256;
    int nb_sc  = (n + 1023) / 1024;
    int nb_gm  = (n + 127) / 128;
    int nb_gat = (int)(((long long)n * 8 + 255) / 256);

    // device pointers to the two buffers
    void* pA = nullptr; cudaGetSymbolAddress(&pA, g_bufA);
    void* pB = nullptr; cudaGetSymbolAddress(&pB, g_bufB);
    __half* bufA = (__half*)pA;
    __half* bufB = (__half*)pB;

    // normalization + CSR build (recomputed every call)
    void* degE_ptr = nullptr;
    cudaGetSymbolAddress(&degE_ptr, g_degE);
    cudaMemsetAsync(degE_ptr, 0, (size_t)n * sizeof(int));
    count_deg_kernel<<<nb_e, 256>>>(dst, E);
    scanA_kernel<<<nb_sc, 256>>>(n);           // also computes g_dis
    scanB_kernel<<<1, 32>>>(nb_sc, n, E);
    scanC_kernel<<<nb_sc, 256>>>(n);
    fill_kernel<<<nb_e, 256>>>(src, dst, E);

    // layer 1: dense GEMM (HMMA) -> msg in bufA
    gemm1_kernel<<<nb_gm, 256>>>(x, W1, n);
    // gather1 + finalize(b1): h1 fp16 -> bufB
    gather_mid_kernel<<<nb_gat, 256>>>(bufA, bufB, b1, n);
    // layer 2 GEMM: h1 @ W2 -> msg in bufA
    gemm_mid_kernel<<<nb_gm, 256>>>(bufB, bufA, W2, n);
    // gather2 + finalize(b2): h2 fp16 -> bufB
    gather_mid_kernel<<<nb_gat, 256>>>(bufA, bufB, b2, n);
    // layer 3 GEMM: h2 @ W3 -> msg in bufA
    gemm_mid_kernel<<<nb_gm, 256>>>(bufB, bufA, W3, n);
    // output: gather msg + bias b3 (fp32)
    final_gather_kernel<<<nb_gat, 256>>>(bufA, b3, out, n);
}